// round 17
// baseline (speedup 1.0000x reference)
#include <cuda_runtime.h>
#include <cuda_bf16.h>

// Table-batched EmbeddingBag forward (SUM pooling).
// T=8 tables, B=8192 batch, D=128 dim, ROWS=200000 rows/table.
// indices: [nnz] int32, offsets: [T*B+1] int32, weights: flat
// [T*ROWS*D] float32. out: [B, T*D] float32.
//
// One warp per bag. Lane l owns floats [4l, 4l+4) of the D=128 row
// (one float4); each row gather is a fully-coalesced 512B read.
// Warp body is the measured optimum across 9 variants (81.9us bench /
// 79.7us ncu, DRAM 77.1% = 6.31 TB/s, reproduced twice to 0.03us):
//  - simple dependent loop, scalar broadcast index loads (4
//    independent in flight via unroll 4)
//  - hoisted per-warp table base + 32-bit within-table offsets
//    (table = 102MB < 4GB) -> shortest index->address->LDG chain
//  - no pipelining / int4 indices / smem staging / cache hints /
//    persistent grid — each measured neutral-to-regressive.
// This round's single bounded experiment: 512-thread CTAs (16 warps)
// halving block count 8192 -> 4096; warp-level SASS unchanged.

#ifndef EMB_T
#define EMB_T 8
#define EMB_B 8192
#define EMB_D 128
#define EMB_ROWS 200000
#endif

#define D4 (EMB_D / 4)   // float4 per row = 32
#define BLOCK_THREADS 512

__global__ __launch_bounds__(BLOCK_THREADS) void emb_bag_sum_kernel(
    const int* __restrict__ indices,
    const int* __restrict__ offsets,
    const float4* __restrict__ weights4,   // weights viewed as float4
    float4* __restrict__ out4,             // out viewed as float4
    int n_bags)
{
    const int warp_id = (blockIdx.x * blockDim.x + threadIdx.x) >> 5;
    const int lane    = threadIdx.x & 31;
    if (warp_id >= n_bags) return;

    const int bag     = warp_id;
    const int feature = bag / EMB_B;        // table id
    const int b       = bag - feature * EMB_B;

    const int start = __ldg(offsets + bag);
    const int end   = __ldg(offsets + bag + 1);

    // Per-warp base: table start + this lane's float4 within the row.
    // Within-table offsets (row * 32 float4, max 6.4M) fit in 32 bits.
    const float4* __restrict__ tbl =
        weights4 + (size_t)feature * EMB_ROWS * D4 + lane;

    float4 acc = make_float4(0.f, 0.f, 0.f, 0.f);

    #pragma unroll 4
    for (int j = start; j < end; ++j) {
        const unsigned row = (unsigned)__ldg(indices + j);
        const float4 v = __ldg(tbl + row * (unsigned)D4);
        acc.x += v.x; acc.y += v.y; acc.z += v.z; acc.w += v.w;
    }

    const size_t o = (size_t)b * (EMB_T * D4) + (size_t)feature * D4 + lane;
    out4[o] = acc;
}

extern "C" void kernel_launch(void* const* d_in, const int* in_sizes, int n_in,
                              void* d_out, int out_size)
{
    const int*   indices = (const int*)d_in[0];
    const int*   offsets = (const int*)d_in[1];
    const float* weights = (const float*)d_in[2];

    const int n_bags = in_sizes[1] - 1;             // T*B
    const int warps_per_block = BLOCK_THREADS / 32; // 16
    const int blocks = (n_bags + warps_per_block - 1) / warps_per_block;

    emb_bag_sum_kernel<<<blocks, BLOCK_THREADS>>>(
        indices, offsets,
        (const float4*)weights, (float4*)d_out, n_bags);
}